// round 1
// baseline (speedup 1.0000x reference)
#include <cuda_runtime.h>
#include <cuda_bf16.h>
#include <math.h>

#define N_NODES 100000
#define N_EDGES 20000
#define N_INC   800000
#define D_IN    256
#define D_HID   16
#define D_OUT   40

// ---------------- scratch (device globals; no allocation allowed) ----------------
__device__ float g_XW1[(size_t)N_NODES * D_HID];   // H @ W1
__device__ float g_e1 [(size_t)N_EDGES * D_HID];   // edge accum / e_feat (layer1)
__device__ float g_eden[N_EDGES];                  // sum of w per edge
__device__ float g_vdeg[N_NODES];                  // incidence count per node
__device__ float g_v1 [(size_t)N_NODES * D_HID];   // node accum -> x (after relu)
__device__ float g_XW2[(size_t)N_NODES * D_OUT];   // x @ W2
__device__ float g_e2 [(size_t)N_EDGES * D_OUT];   // edge accum / e_feat (layer2)

// ---------------- helpers ----------------
__device__ __forceinline__ void red_add_v4(float* p, float a, float b, float c, float d) {
    asm volatile("red.global.add.v4.f32 [%0], {%1,%2,%3,%4};"
                 :: "l"(p), "f"(a), "f"(b), "f"(c), "f"(d) : "memory");
}

__global__ void zero4_kernel(float4* p, int n4) {
    int i = blockIdx.x * blockDim.x + threadIdx.x;
    if (i < n4) p[i] = make_float4(0.f, 0.f, 0.f, 0.f);
}

// ---------------- degree / denominator (shared by both layers) ----------------
__global__ void deg_kernel(const int* __restrict__ ni, const int* __restrict__ ei,
                           const float* __restrict__ w) {
    int i = blockIdx.x * blockDim.x + threadIdx.x;
    if (i >= N_INC) return;
    int v = ni[i];
    int e = ei[i];
    float wv = __ldg(&w[v]);
    atomicAdd(&g_eden[e], wv);   // ptxas -> REDG (no return used)
    atomicAdd(&g_vdeg[v], 1.f);
}

// ---------------- GEMM1: XW1 = H @ W1  (100000x256 @ 256x16) ----------------
__global__ void gemm1_kernel(const float* __restrict__ H, const float* __restrict__ W1) {
    __shared__ float sW[D_IN * D_HID];
    for (int i = threadIdx.x; i < D_IN * D_HID; i += blockDim.x) sW[i] = W1[i];
    __syncthreads();

    int row = blockIdx.x * blockDim.x + threadIdx.x;
    if (row >= N_NODES) return;

    float acc[D_HID];
#pragma unroll
    for (int j = 0; j < D_HID; j++) acc[j] = 0.f;

    const float4* hp = reinterpret_cast<const float4*>(H + (size_t)row * D_IN);
#pragma unroll 4
    for (int k4 = 0; k4 < D_IN / 4; k4++) {
        float4 hv = hp[k4];
        const float* wr = &sW[k4 * 4 * D_HID];
        float xs[4] = {hv.x, hv.y, hv.z, hv.w};
#pragma unroll
        for (int c = 0; c < 4; c++) {
            const float4* w4 = reinterpret_cast<const float4*>(wr + c * D_HID);
            float4 wa = w4[0], wb = w4[1], wc = w4[2], wd = w4[3];
            float x = xs[c];
            acc[0]  += x * wa.x;  acc[1]  += x * wa.y;  acc[2]  += x * wa.z;  acc[3]  += x * wa.w;
            acc[4]  += x * wb.x;  acc[5]  += x * wb.y;  acc[6]  += x * wb.z;  acc[7]  += x * wb.w;
            acc[8]  += x * wc.x;  acc[9]  += x * wc.y;  acc[10] += x * wc.z;  acc[11] += x * wc.w;
            acc[12] += x * wd.x;  acc[13] += x * wd.y;  acc[14] += x * wd.z;  acc[15] += x * wd.w;
        }
    }
    float4* op = reinterpret_cast<float4*>(g_XW1 + (size_t)row * D_HID);
    op[0] = make_float4(acc[0],  acc[1],  acc[2],  acc[3]);
    op[1] = make_float4(acc[4],  acc[5],  acc[6],  acc[7]);
    op[2] = make_float4(acc[8],  acc[9],  acc[10], acc[11]);
    op[3] = make_float4(acc[12], acc[13], acc[14], acc[15]);
}

// ---------------- layer1 scatter: node -> edge (weighted) ----------------
__global__ void scat1a_kernel(const int* __restrict__ ni, const int* __restrict__ ei,
                              const float* __restrict__ w) {
    int i = blockIdx.x * blockDim.x + threadIdx.x;
    if (i >= N_INC) return;
    int v = ni[i];
    int e = ei[i];
    float wv = __ldg(&w[v]);
    const float4* xr = reinterpret_cast<const float4*>(g_XW1 + (size_t)v * D_HID);
    float* er = g_e1 + (size_t)e * D_HID;
#pragma unroll
    for (int q = 0; q < 4; q++) {
        float4 t = __ldg(&xr[q]);
        red_add_v4(er + q * 4, t.x * wv, t.y * wv, t.z * wv, t.w * wv);
    }
}

// e_feat = e_sum / max(e_den, 1e-6)  (in place)
__global__ void edgefin1_kernel() {
    int i = blockIdx.x * blockDim.x + threadIdx.x;
    if (i >= N_EDGES * D_HID) return;
    int e = i / D_HID;
    g_e1[i] = g_e1[i] / fmaxf(g_eden[e], 1e-6f);
}

// ---------------- layer1 scatter: edge -> node ----------------
__global__ void scat1b_kernel(const int* __restrict__ ni, const int* __restrict__ ei) {
    int i = blockIdx.x * blockDim.x + threadIdx.x;
    if (i >= N_INC) return;
    int v = ni[i];
    int e = ei[i];
    const float4* er = reinterpret_cast<const float4*>(g_e1 + (size_t)e * D_HID);
    float* vr = g_v1 + (size_t)v * D_HID;
#pragma unroll
    for (int q = 0; q < 4; q++) {
        float4 t = __ldg(&er[q]);
        red_add_v4(vr + q * 4, t.x, t.y, t.z, t.w);
    }
}

// x = relu(v_sum / max(v_deg,1) + b1)   (in place on g_v1)
__global__ void nodefin1_kernel(const float* __restrict__ b1) {
    int i = blockIdx.x * blockDim.x + threadIdx.x;
    if (i >= N_NODES * D_HID) return;
    int v = i / D_HID;
    int j = i - v * D_HID;
    float x = g_v1[i] / fmaxf(g_vdeg[v], 1.f) + __ldg(&b1[j]);
    g_v1[i] = fmaxf(x, 0.f);
}

// ---------------- GEMM2: XW2 = x @ W2  (100000x16 @ 16x40) ----------------
__global__ void gemm2_kernel(const float* __restrict__ W2) {
    __shared__ float sW[D_HID * D_OUT];
    for (int i = threadIdx.x; i < D_HID * D_OUT; i += blockDim.x) sW[i] = W2[i];
    __syncthreads();

    int row = blockIdx.x * blockDim.x + threadIdx.x;
    if (row >= N_NODES) return;

    float xv[D_HID];
    const float4* xp = reinterpret_cast<const float4*>(g_v1 + (size_t)row * D_HID);
#pragma unroll
    for (int q = 0; q < 4; q++) {
        float4 t = xp[q];
        xv[q * 4 + 0] = t.x; xv[q * 4 + 1] = t.y; xv[q * 4 + 2] = t.z; xv[q * 4 + 3] = t.w;
    }

    float acc[D_OUT];
#pragma unroll
    for (int j = 0; j < D_OUT; j++) acc[j] = 0.f;

#pragma unroll
    for (int k = 0; k < D_HID; k++) {
        float x = xv[k];
        const float4* w4 = reinterpret_cast<const float4*>(&sW[k * D_OUT]);
#pragma unroll
        for (int j4 = 0; j4 < D_OUT / 4; j4++) {
            float4 wv = w4[j4];
            acc[j4 * 4 + 0] += x * wv.x;
            acc[j4 * 4 + 1] += x * wv.y;
            acc[j4 * 4 + 2] += x * wv.z;
            acc[j4 * 4 + 3] += x * wv.w;
        }
    }
    float4* op = reinterpret_cast<float4*>(g_XW2 + (size_t)row * D_OUT);
#pragma unroll
    for (int j4 = 0; j4 < D_OUT / 4; j4++)
        op[j4] = make_float4(acc[j4 * 4 + 0], acc[j4 * 4 + 1], acc[j4 * 4 + 2], acc[j4 * 4 + 3]);
}

// ---------------- layer2 scatters ----------------
__global__ void scat2a_kernel(const int* __restrict__ ni, const int* __restrict__ ei,
                              const float* __restrict__ w) {
    int i = blockIdx.x * blockDim.x + threadIdx.x;
    if (i >= N_INC) return;
    int v = ni[i];
    int e = ei[i];
    float wv = __ldg(&w[v]);
    const float4* xr = reinterpret_cast<const float4*>(g_XW2 + (size_t)v * D_OUT);
    float* er = g_e2 + (size_t)e * D_OUT;
#pragma unroll
    for (int q = 0; q < D_OUT / 4; q++) {
        float4 t = __ldg(&xr[q]);
        red_add_v4(er + q * 4, t.x * wv, t.y * wv, t.z * wv, t.w * wv);
    }
}

__global__ void edgefin2_kernel() {
    int i = blockIdx.x * blockDim.x + threadIdx.x;
    if (i >= N_EDGES * D_OUT) return;
    int e = i / D_OUT;
    g_e2[i] = g_e2[i] / fmaxf(g_eden[e], 1e-6f);
}

__global__ void scat2b_kernel(const int* __restrict__ ni, const int* __restrict__ ei,
                              float* __restrict__ out) {
    int i = blockIdx.x * blockDim.x + threadIdx.x;
    if (i >= N_INC) return;
    int v = ni[i];
    int e = ei[i];
    const float4* er = reinterpret_cast<const float4*>(g_e2 + (size_t)e * D_OUT);
    float* vr = out + (size_t)v * D_OUT;
#pragma unroll
    for (int q = 0; q < D_OUT / 4; q++) {
        float4 t = __ldg(&er[q]);
        red_add_v4(vr + q * 4, t.x, t.y, t.z, t.w);
    }
}

// ---------------- finalize: /deg + b2, log_softmax (warp per row, in place) ----
__global__ void finalize_kernel(float* __restrict__ out, const float* __restrict__ b2) {
    int gtid = blockIdx.x * blockDim.x + threadIdx.x;
    int row  = gtid >> 5;
    int lane = gtid & 31;
    if (row >= N_NODES) return;

    float inv = 1.f / fmaxf(g_vdeg[row], 1.f);
    float* r = out + (size_t)row * D_OUT;

    float v0 = r[lane] * inv + __ldg(&b2[lane]);                    // lane 0..31 < 40
    bool  has2 = (lane + 32) < D_OUT;
    float v1 = has2 ? (r[lane + 32] * inv + __ldg(&b2[lane + 32])) : -INFINITY;

    float m = fmaxf(v0, v1);
#pragma unroll
    for (int off = 16; off > 0; off >>= 1)
        m = fmaxf(m, __shfl_xor_sync(0xFFFFFFFFu, m, off));

    float s = __expf(v0 - m) + (has2 ? __expf(v1 - m) : 0.f);
#pragma unroll
    for (int off = 16; off > 0; off >>= 1)
        s += __shfl_xor_sync(0xFFFFFFFFu, s, off);

    float lse = m + __logf(s);
    r[lane] = v0 - lse;
    if (has2) r[lane + 32] = v1 - lse;
}

// ---------------- launch ----------------
extern "C" void kernel_launch(void* const* d_in, const int* in_sizes, int n_in,
                              void* d_out, int out_size) {
    const float* H   = (const float*)d_in[0];
    const float* w   = (const float*)d_in[1];
    const int*   ni  = (const int*)  d_in[2];
    const int*   ei  = (const int*)  d_in[3];
    const float* W1  = (const float*)d_in[4];
    const float* b1  = (const float*)d_in[5];
    const float* W2  = (const float*)d_in[6];
    const float* b2  = (const float*)d_in[7];
    float*       out = (float*)d_out;

    float *p_e1, *p_eden, *p_vdeg, *p_v1, *p_e2;
    cudaGetSymbolAddress((void**)&p_e1,   g_e1);
    cudaGetSymbolAddress((void**)&p_eden, g_eden);
    cudaGetSymbolAddress((void**)&p_vdeg, g_vdeg);
    cudaGetSymbolAddress((void**)&p_v1,   g_v1);
    cudaGetSymbolAddress((void**)&p_e2,   g_e2);

    const int T = 256;
    auto blocks = [](long n, int t) { return (int)((n + t - 1) / t); };

    // zero accumulators (all sizes divisible by 4)
    zero4_kernel<<<blocks(N_EDGES * D_HID / 4, T), T>>>((float4*)p_e1,   N_EDGES * D_HID / 4);
    zero4_kernel<<<blocks(N_EDGES / 4, T), T>>>((float4*)p_eden, N_EDGES / 4);
    zero4_kernel<<<blocks(N_NODES / 4, T), T>>>((float4*)p_vdeg, N_NODES / 4);
    zero4_kernel<<<blocks(N_NODES * D_HID / 4, T), T>>>((float4*)p_v1,   N_NODES * D_HID / 4);
    zero4_kernel<<<blocks(N_EDGES * D_OUT / 4, T), T>>>((float4*)p_e2,   N_EDGES * D_OUT / 4);
    zero4_kernel<<<blocks((long)N_NODES * D_OUT / 4, T), T>>>((float4*)out, N_NODES * D_OUT / 4);

    // degrees / denominators (shared by both layers)
    deg_kernel<<<blocks(N_INC, T), T>>>(ni, ei, w);

    // layer 1
    gemm1_kernel<<<blocks(N_NODES, T), T>>>(H, W1);
    scat1a_kernel<<<blocks(N_INC, T), T>>>(ni, ei, w);
    edgefin1_kernel<<<blocks(N_EDGES * D_HID, T), T>>>();
    scat1b_kernel<<<blocks(N_INC, T), T>>>(ni, ei);
    nodefin1_kernel<<<blocks(N_NODES * D_HID, T), T>>>(b1);

    // layer 2
    gemm2_kernel<<<blocks(N_NODES, T), T>>>(W2);
    scat2a_kernel<<<blocks(N_INC, T), T>>>(ni, ei, w);
    edgefin2_kernel<<<blocks(N_EDGES * D_OUT, T), T>>>();
    scat2b_kernel<<<blocks(N_INC, T), T>>>(ni, ei, out);

    // epilogue: bias + log_softmax
    finalize_kernel<<<blocks((long)N_NODES * 32, T), T>>>(out, b2);
}

// round 2
// speedup vs baseline: 1.3887x; 1.3887x over previous
#include <cuda_runtime.h>
#include <cuda_bf16.h>
#include <math.h>

#define N_NODES 100000
#define N_EDGES 20000
#define N_INC   800000
#define D_IN    256
#define D_HID   16
#define D_OUT   40

// ---------------- scratch (device globals; no allocation allowed) ----------------
__device__ float g_XW1[(size_t)N_NODES * D_HID];   // H @ W1
__device__ float g_e1 [(size_t)N_EDGES * D_HID];   // edge accum (layer1, raw sums)
__device__ float g_eden[N_EDGES];                  // sum of w per edge -> 1/max(.,1e-6)
__device__ float g_vdeg[N_NODES];                  // incidence count  -> 1/max(.,1)
__device__ float g_v1 [(size_t)N_NODES * D_HID];   // node accum (layer1, raw sums)
__device__ float g_XW2[(size_t)N_NODES * D_OUT];   // relu-feat @ W2
__device__ float g_e2 [(size_t)N_EDGES * D_OUT];   // edge accum (layer2, raw sums)

// ---------------- helpers ----------------
__device__ __forceinline__ void red_add_v4(float* p, float a, float b, float c, float d) {
    asm volatile("red.global.add.v4.f32 [%0], {%1,%2,%3,%4};"
                 :: "l"(p), "f"(a), "f"(b), "f"(c), "f"(d) : "memory");
}

// ---------------- zero everything that gets atomically accumulated ------------
#define Z1 (N_EDGES * D_HID / 4)            // g_e1   : 80000
#define Z2 (N_EDGES / 4)                    // g_eden :  5000
#define Z3 (N_NODES / 4)                    // g_vdeg : 25000
#define Z4 (N_NODES * D_HID / 4)            // g_v1   : 400000
#define Z5 (N_EDGES * D_OUT / 4)            // g_e2   : 200000
#define Z6 (N_NODES * D_OUT / 4)            // out    : 1000000
#define ZTOT (Z1 + Z2 + Z3 + Z4 + Z5 + Z6)  // 1710000

__global__ void zero_all_kernel(float4* out) {
    int i = blockIdx.x * blockDim.x + threadIdx.x;
    if (i >= ZTOT) return;
    float4 z = make_float4(0.f, 0.f, 0.f, 0.f);
    if (i < Z1) { reinterpret_cast<float4*>(g_e1)[i] = z; return; }
    i -= Z1;
    if (i < Z2) { reinterpret_cast<float4*>(g_eden)[i] = z; return; }
    i -= Z2;
    if (i < Z3) { reinterpret_cast<float4*>(g_vdeg)[i] = z; return; }
    i -= Z3;
    if (i < Z4) { reinterpret_cast<float4*>(g_v1)[i] = z; return; }
    i -= Z4;
    if (i < Z5) { reinterpret_cast<float4*>(g_e2)[i] = z; return; }
    i -= Z5;
    out[i] = z;
}

// ---------------- degrees / denominators (shared by both layers) --------------
__global__ void deg_kernel(const int* __restrict__ ni, const int* __restrict__ ei,
                           const float* __restrict__ w) {
    int i = blockIdx.x * blockDim.x + threadIdx.x;
    if (i >= N_INC) return;
    int v = ni[i];
    int e = ei[i];
    atomicAdd(&g_eden[e], __ldg(&w[v]));
    atomicAdd(&g_vdeg[v], 1.f);
}

// convert both denominators to inverses (in place)
__global__ void inv_kernel() {
    int i = blockIdx.x * blockDim.x + threadIdx.x;
    if (i < N_EDGES) g_eden[i] = __frcp_rn(fmaxf(g_eden[i], 1e-6f));
    else if (i < N_EDGES + N_NODES) {
        int v = i - N_EDGES;
        g_vdeg[v] = __frcp_rn(fmaxf(g_vdeg[v], 1.f));
    }
}

// ---------------- GEMM1: XW1 = H @ W1  (100000x256 @ 256x16) ----------------
__global__ void gemm1_kernel(const float* __restrict__ H, const float* __restrict__ W1) {
    __shared__ float sW[D_IN * D_HID];
    for (int i = threadIdx.x; i < D_IN * D_HID; i += blockDim.x) sW[i] = W1[i];
    __syncthreads();

    int row = blockIdx.x * blockDim.x + threadIdx.x;
    if (row >= N_NODES) return;

    float acc[D_HID];
#pragma unroll
    for (int j = 0; j < D_HID; j++) acc[j] = 0.f;

    const float4* hp = reinterpret_cast<const float4*>(H + (size_t)row * D_IN);
#pragma unroll 4
    for (int k4 = 0; k4 < D_IN / 4; k4++) {
        float4 hv = hp[k4];
        const float* wr = &sW[k4 * 4 * D_HID];
        float xs[4] = {hv.x, hv.y, hv.z, hv.w};
#pragma unroll
        for (int c = 0; c < 4; c++) {
            const float4* w4 = reinterpret_cast<const float4*>(wr + c * D_HID);
            float4 wa = w4[0], wb = w4[1], wc = w4[2], wd = w4[3];
            float x = xs[c];
            acc[0]  += x * wa.x;  acc[1]  += x * wa.y;  acc[2]  += x * wa.z;  acc[3]  += x * wa.w;
            acc[4]  += x * wb.x;  acc[5]  += x * wb.y;  acc[6]  += x * wb.z;  acc[7]  += x * wb.w;
            acc[8]  += x * wc.x;  acc[9]  += x * wc.y;  acc[10] += x * wc.z;  acc[11] += x * wc.w;
            acc[12] += x * wd.x;  acc[13] += x * wd.y;  acc[14] += x * wd.z;  acc[15] += x * wd.w;
        }
    }
    float4* op = reinterpret_cast<float4*>(g_XW1 + (size_t)row * D_HID);
    op[0] = make_float4(acc[0],  acc[1],  acc[2],  acc[3]);
    op[1] = make_float4(acc[4],  acc[5],  acc[6],  acc[7]);
    op[2] = make_float4(acc[8],  acc[9],  acc[10], acc[11]);
    op[3] = make_float4(acc[12], acc[13], acc[14], acc[15]);
}

// ---------------- layer1 scatter A: node -> edge (weighted) -------------------
// thread per (incidence, 16B chunk): 4 chunks of D_HID=16
__global__ void scat1a_kernel(const int* __restrict__ ni, const int* __restrict__ ei,
                              const float* __restrict__ w) {
    int t = blockIdx.x * blockDim.x + threadIdx.x;
    if (t >= N_INC * 4) return;
    int i = t >> 2, q = t & 3;
    int v = __ldg(&ni[i]);
    int e = __ldg(&ei[i]);
    float wv = __ldg(&w[v]);
    float4 x = __ldg(reinterpret_cast<const float4*>(g_XW1 + (size_t)v * D_HID) + q);
    red_add_v4(g_e1 + (size_t)e * D_HID + q * 4, x.x * wv, x.y * wv, x.z * wv, x.w * wv);
}

// ---------------- layer1 scatter B: edge -> node (applies 1/e_den) ------------
__global__ void scat1b_kernel(const int* __restrict__ ni, const int* __restrict__ ei) {
    int t = blockIdx.x * blockDim.x + threadIdx.x;
    if (t >= N_INC * 4) return;
    int i = t >> 2, q = t & 3;
    int v = __ldg(&ni[i]);
    int e = __ldg(&ei[i]);
    float inv = __ldg(&g_eden[e]);
    float4 x = __ldg(reinterpret_cast<const float4*>(g_e1 + (size_t)e * D_HID) + q);
    red_add_v4(g_v1 + (size_t)v * D_HID + q * 4, x.x * inv, x.y * inv, x.z * inv, x.w * inv);
}

// ---------------- GEMM2 fused with nodefin1: x=relu(v1/deg+b1); XW2=x@W2 ------
__global__ void gemm2_kernel(const float* __restrict__ W2, const float* __restrict__ b1) {
    __shared__ float sW[D_HID * D_OUT];
    __shared__ float sB[D_HID];
    for (int i = threadIdx.x; i < D_HID * D_OUT; i += blockDim.x) sW[i] = W2[i];
    if (threadIdx.x < D_HID) sB[threadIdx.x] = b1[threadIdx.x];
    __syncthreads();

    int row = blockIdx.x * blockDim.x + threadIdx.x;
    if (row >= N_NODES) return;

    float inv = __ldg(&g_vdeg[row]);   // already 1/max(deg,1)
    float xv[D_HID];
    const float4* xp = reinterpret_cast<const float4*>(g_v1 + (size_t)row * D_HID);
#pragma unroll
    for (int q = 0; q < 4; q++) {
        float4 tq = xp[q];
        xv[q * 4 + 0] = fmaxf(tq.x * inv + sB[q * 4 + 0], 0.f);
        xv[q * 4 + 1] = fmaxf(tq.y * inv + sB[q * 4 + 1], 0.f);
        xv[q * 4 + 2] = fmaxf(tq.z * inv + sB[q * 4 + 2], 0.f);
        xv[q * 4 + 3] = fmaxf(tq.w * inv + sB[q * 4 + 3], 0.f);
    }

    float acc[D_OUT];
#pragma unroll
    for (int j = 0; j < D_OUT; j++) acc[j] = 0.f;

#pragma unroll
    for (int k = 0; k < D_HID; k++) {
        float x = xv[k];
        const float4* w4 = reinterpret_cast<const float4*>(&sW[k * D_OUT]);
#pragma unroll
        for (int j4 = 0; j4 < D_OUT / 4; j4++) {
            float4 wv = w4[j4];
            acc[j4 * 4 + 0] += x * wv.x;
            acc[j4 * 4 + 1] += x * wv.y;
            acc[j4 * 4 + 2] += x * wv.z;
            acc[j4 * 4 + 3] += x * wv.w;
        }
    }
    float4* op = reinterpret_cast<float4*>(g_XW2 + (size_t)row * D_OUT);
#pragma unroll
    for (int j4 = 0; j4 < D_OUT / 4; j4++)
        op[j4] = make_float4(acc[j4 * 4 + 0], acc[j4 * 4 + 1], acc[j4 * 4 + 2], acc[j4 * 4 + 3]);
}

// ---------------- layer2 scatter A: node -> edge (weighted), 10 chunks -------
__global__ void scat2a_kernel(const int* __restrict__ ni, const int* __restrict__ ei,
                              const float* __restrict__ w) {
    int t = blockIdx.x * blockDim.x + threadIdx.x;
    if (t >= N_INC * 10) return;
    int i = t / 10, q = t - i * 10;
    int v = __ldg(&ni[i]);
    int e = __ldg(&ei[i]);
    float wv = __ldg(&w[v]);
    float4 x = __ldg(reinterpret_cast<const float4*>(g_XW2 + (size_t)v * D_OUT) + q);
    red_add_v4(g_e2 + (size_t)e * D_OUT + q * 4, x.x * wv, x.y * wv, x.z * wv, x.w * wv);
}

// ---------------- layer2 scatter B: edge -> node (applies 1/e_den) ------------
__global__ void scat2b_kernel(const int* __restrict__ ni, const int* __restrict__ ei,
                              float* __restrict__ out) {
    int t = blockIdx.x * blockDim.x + threadIdx.x;
    if (t >= N_INC * 10) return;
    int i = t / 10, q = t - i * 10;
    int v = __ldg(&ni[i]);
    int e = __ldg(&ei[i]);
    float inv = __ldg(&g_eden[e]);
    float4 x = __ldg(reinterpret_cast<const float4*>(g_e2 + (size_t)e * D_OUT) + q);
    red_add_v4(out + (size_t)v * D_OUT + q * 4, x.x * inv, x.y * inv, x.z * inv, x.w * inv);
}

// ---------------- finalize: /deg + b2, log_softmax (warp per row, in place) ---
__global__ void finalize_kernel(float* __restrict__ out, const float* __restrict__ b2) {
    int gtid = blockIdx.x * blockDim.x + threadIdx.x;
    int row  = gtid >> 5;
    int lane = gtid & 31;
    if (row >= N_NODES) return;

    float inv = __ldg(&g_vdeg[row]);   // already 1/max(deg,1)
    float* r = out + (size_t)row * D_OUT;

    float v0 = r[lane] * inv + __ldg(&b2[lane]);
    bool  has2 = (lane + 32) < D_OUT;
    float v1 = has2 ? (r[lane + 32] * inv + __ldg(&b2[lane + 32])) : -INFINITY;

    float m = fmaxf(v0, v1);
#pragma unroll
    for (int off = 16; off > 0; off >>= 1)
        m = fmaxf(m, __shfl_xor_sync(0xFFFFFFFFu, m, off));

    float s = __expf(v0 - m) + (has2 ? __expf(v1 - m) : 0.f);
#pragma unroll
    for (int off = 16; off > 0; off >>= 1)
        s += __shfl_xor_sync(0xFFFFFFFFu, s, off);

    float lse = m + __logf(s);
    r[lane] = v0 - lse;
    if (has2) r[lane + 32] = v1 - lse;
}

// ---------------- launch ----------------
extern "C" void kernel_launch(void* const* d_in, const int* in_sizes, int n_in,
                              void* d_out, int out_size) {
    const float* H   = (const float*)d_in[0];
    const float* w   = (const float*)d_in[1];
    const int*   ni  = (const int*)  d_in[2];
    const int*   ei  = (const int*)  d_in[3];
    const float* W1  = (const float*)d_in[4];
    const float* b1  = (const float*)d_in[5];
    const float* W2  = (const float*)d_in[6];
    const float* b2  = (const float*)d_in[7];
    float*       out = (float*)d_out;

    const int T = 256;
    auto blocks = [](long n, int t) { return (int)((n + t - 1) / t); };

    zero_all_kernel<<<blocks(ZTOT, T), T>>>((float4*)out);
    deg_kernel<<<blocks(N_INC, T), T>>>(ni, ei, w);
    gemm1_kernel<<<blocks(N_NODES, T), T>>>(H, W1);      // independent of deg; overlaps tail
    inv_kernel<<<blocks(N_EDGES + N_NODES, T), T>>>();

    scat1a_kernel<<<blocks((long)N_INC * 4, T), T>>>(ni, ei, w);
    scat1b_kernel<<<blocks((long)N_INC * 4, T), T>>>(ni, ei);
    gemm2_kernel<<<blocks(N_NODES, T), T>>>(W2, b1);

    scat2a_kernel<<<blocks((long)N_INC * 10, T), T>>>(ni, ei, w);
    scat2b_kernel<<<blocks((long)N_INC * 10, T), T>>>(ni, ei, out);

    finalize_kernel<<<blocks((long)N_NODES * 32, T), T>>>(out, b2);
}

// round 3
// speedup vs baseline: 1.4600x; 1.0513x over previous
#include <cuda_runtime.h>
#include <cuda_bf16.h>
#include <math.h>

#define N_NODES 100000
#define N_EDGES 20000
#define N_INC   800000
#define D_IN    256
#define D_HID   16
#define D_OUT   40
#define PAD_E   128     // max edge degree bucket (mean 40)
#define PAD_V   64      // max node degree bucket (mean 8)

// ---------------- scratch (device globals) ----------------
__device__ float g_XW1[(size_t)N_NODES * D_HID];   // H @ W1
__device__ float g_e1 [(size_t)N_EDGES * D_HID];   // e_feat layer1 (normalized)
__device__ float g_XW2[(size_t)N_NODES * D_OUT];   // relu-feat @ W2
__device__ float g_e2 [(size_t)N_EDGES * D_OUT];   // e_feat layer2 (normalized)
__device__ int   g_cnt_e[N_EDGES];
__device__ int   g_cnt_v[N_NODES];
__device__ int   g_buf_e[(size_t)N_EDGES * PAD_E]; // member node indices per edge
__device__ int   g_buf_v[(size_t)N_NODES * PAD_V]; // incident edge indices per node

// ---------------- zero counters ----------------
#define ZC ((N_EDGES + N_NODES) / 4)
__global__ void zero_cnt_kernel() {
    int i = blockIdx.x * blockDim.x + threadIdx.x;
    if (i >= ZC) return;
    int4 z = make_int4(0, 0, 0, 0);
    if (i < N_EDGES / 4) reinterpret_cast<int4*>(g_cnt_e)[i] = z;
    else reinterpret_cast<int4*>(g_cnt_v)[i - N_EDGES / 4] = z;
}

// ---------------- build padded buckets ----------------
__global__ void fill_kernel(const int* __restrict__ ni, const int* __restrict__ ei) {
    int i = blockIdx.x * blockDim.x + threadIdx.x;
    if (i >= N_INC) return;
    int v = __ldg(&ni[i]);
    int e = __ldg(&ei[i]);
    int se = atomicAdd(&g_cnt_e[e], 1);
    if (se < PAD_E) g_buf_e[(size_t)e * PAD_E + se] = v;
    int sv = atomicAdd(&g_cnt_v[v], 1);
    if (sv < PAD_V) g_buf_v[(size_t)v * PAD_V + sv] = e;
}

// ---------------- GEMM1: XW1 = H @ W1  (100000x256 @ 256x16) ----------------
__global__ void gemm1_kernel(const float* __restrict__ H, const float* __restrict__ W1) {
    __shared__ float sW[D_IN * D_HID];
    for (int i = threadIdx.x; i < D_IN * D_HID; i += blockDim.x) sW[i] = W1[i];
    __syncthreads();

    int row = blockIdx.x * blockDim.x + threadIdx.x;
    if (row >= N_NODES) return;

    float acc[D_HID];
#pragma unroll
    for (int j = 0; j < D_HID; j++) acc[j] = 0.f;

    const float4* hp = reinterpret_cast<const float4*>(H + (size_t)row * D_IN);
#pragma unroll 4
    for (int k4 = 0; k4 < D_IN / 4; k4++) {
        float4 hv = hp[k4];
        const float* wr = &sW[k4 * 4 * D_HID];
        float xs[4] = {hv.x, hv.y, hv.z, hv.w};
#pragma unroll
        for (int c = 0; c < 4; c++) {
            const float4* w4 = reinterpret_cast<const float4*>(wr + c * D_HID);
            float4 wa = w4[0], wb = w4[1], wc = w4[2], wd = w4[3];
            float x = xs[c];
            acc[0]  += x * wa.x;  acc[1]  += x * wa.y;  acc[2]  += x * wa.z;  acc[3]  += x * wa.w;
            acc[4]  += x * wb.x;  acc[5]  += x * wb.y;  acc[6]  += x * wb.z;  acc[7]  += x * wb.w;
            acc[8]  += x * wc.x;  acc[9]  += x * wc.y;  acc[10] += x * wc.z;  acc[11] += x * wc.w;
            acc[12] += x * wd.x;  acc[13] += x * wd.y;  acc[14] += x * wd.z;  acc[15] += x * wd.w;
        }
    }
    float4* op = reinterpret_cast<float4*>(g_XW1 + (size_t)row * D_HID);
    op[0] = make_float4(acc[0],  acc[1],  acc[2],  acc[3]);
    op[1] = make_float4(acc[4],  acc[5],  acc[6],  acc[7]);
    op[2] = make_float4(acc[8],  acc[9],  acc[10], acc[11]);
    op[3] = make_float4(acc[12], acc[13], acc[14], acc[15]);
}

// ---------------- edge gather 1: e1[e] = (Σ w_v * XW1[v]) / max(Σ w_v, 1e-6) --
// warp per edge; two members per iteration (one per half-warp); lane owns feature (lane&15)
__global__ void edge_gather1_kernel(const float* __restrict__ w) {
    int warp = (blockIdx.x * blockDim.x + threadIdx.x) >> 5;
    int lane = threadIdx.x & 31;
    if (warp >= N_EDGES) return;
    int e = warp;
    int cnt = min(__ldg(&g_cnt_e[e]), PAD_E);
    int half = lane >> 4, fl = lane & 15;

    float acc = 0.f, wsum = 0.f;
    const int* buf = g_buf_e + (size_t)e * PAD_E;
    for (int m = half; m < cnt; m += 2) {
        int v = __ldg(&buf[m]);
        float wv = __ldg(&w[v]);
        acc  += wv * __ldg(&g_XW1[(size_t)v * D_HID + fl]);
        wsum += wv;
    }
    acc  += __shfl_xor_sync(0xFFFFFFFFu, acc, 16);
    wsum += __shfl_xor_sync(0xFFFFFFFFu, wsum, 16);
    float inv = __frcp_rn(fmaxf(wsum, 1e-6f));
    if (lane < D_HID) g_e1[(size_t)e * D_HID + lane] = acc * inv;
}

// ---------------- node gather 1 fused with relu + GEMM2 ----------------------
// warp per node; x[16] = relu(mean(e1 rows) + b1); XW2[row] = x @ W2
__global__ void node_gather1_gemm2_kernel(const float* __restrict__ W2,
                                          const float* __restrict__ b1) {
    __shared__ float sW[D_HID * D_OUT];
    __shared__ float sB[D_HID];
    for (int i = threadIdx.x; i < D_HID * D_OUT; i += blockDim.x) sW[i] = W2[i];
    if (threadIdx.x < D_HID) sB[threadIdx.x] = b1[threadIdx.x];
    __syncthreads();

    int warp = (blockIdx.x * blockDim.x + threadIdx.x) >> 5;
    int lane = threadIdx.x & 31;
    if (warp >= N_NODES) return;
    int v = warp;
    int cnt = min(__ldg(&g_cnt_v[v]), PAD_V);
    int half = lane >> 4, fl = lane & 15;

    float acc = 0.f;
    const int* buf = g_buf_v + (size_t)v * PAD_V;
    for (int m = half; m < cnt; m += 2) {
        int e = __ldg(&buf[m]);
        acc += __ldg(&g_e1[(size_t)e * D_HID + fl]);
    }
    acc += __shfl_xor_sync(0xFFFFFFFFu, acc, 16);

    float invd = __frcp_rn(fmaxf((float)cnt, 1.f));
    float x = fmaxf(acc * invd + sB[fl], 0.f);   // lane holds x[fl] (dup across halves)

    float a0 = 0.f, a1 = 0.f;
#pragma unroll
    for (int k = 0; k < D_HID; k++) {
        float xk = __shfl_sync(0xFFFFFFFFu, x, k);   // lane k holds x[k]
        a0 += xk * sW[k * D_OUT + lane];
        if (lane < D_OUT - 32) a1 += xk * sW[k * D_OUT + 32 + lane];
    }
    g_XW2[(size_t)v * D_OUT + lane] = a0;
    if (lane < D_OUT - 32) g_XW2[(size_t)v * D_OUT + 32 + lane] = a1;
}

// ---------------- edge gather 2: e2[e] = (Σ w_v * XW2[v]) / max(Σ w_v, 1e-6) --
// warp per edge; whole warp per member (lane j covers cols j and j+32)
__global__ void edge_gather2_kernel(const float* __restrict__ w) {
    int warp = (blockIdx.x * blockDim.x + threadIdx.x) >> 5;
    int lane = threadIdx.x & 31;
    if (warp >= N_EDGES) return;
    int e = warp;
    int cnt = min(__ldg(&g_cnt_e[e]), PAD_E);

    float a0 = 0.f, a1 = 0.f, wsum = 0.f;
    const int* buf = g_buf_e + (size_t)e * PAD_E;
    for (int m = 0; m < cnt; m++) {
        int v = __ldg(&buf[m]);
        float wv = __ldg(&w[v]);
        wsum += wv;
        const float* xr = g_XW2 + (size_t)v * D_OUT;
        a0 += wv * __ldg(&xr[lane]);
        if (lane < D_OUT - 32) a1 += wv * __ldg(&xr[32 + lane]);
    }
    float inv = __frcp_rn(fmaxf(wsum, 1e-6f));
    g_e2[(size_t)e * D_OUT + lane] = a0 * inv;
    if (lane < D_OUT - 32) g_e2[(size_t)e * D_OUT + 32 + lane] = a1 * inv;
}

// ---------------- node gather 2 fused with bias + log_softmax ----------------
// warp per node; writes d_out directly
__global__ void node_gather2_fin_kernel(float* __restrict__ out,
                                        const float* __restrict__ b2) {
    int warp = (blockIdx.x * blockDim.x + threadIdx.x) >> 5;
    int lane = threadIdx.x & 31;
    if (warp >= N_NODES) return;
    int v = warp;
    int cnt = min(__ldg(&g_cnt_v[v]), PAD_V);

    float a0 = 0.f, a1 = 0.f;
    const int* buf = g_buf_v + (size_t)v * PAD_V;
    for (int m = 0; m < cnt; m++) {
        int e = __ldg(&buf[m]);
        const float* er = g_e2 + (size_t)e * D_OUT;
        a0 += __ldg(&er[lane]);
        if (lane < D_OUT - 32) a1 += __ldg(&er[32 + lane]);
    }
    float invd = __frcp_rn(fmaxf((float)cnt, 1.f));
    bool has2 = lane < (D_OUT - 32);
    float v0 = a0 * invd + __ldg(&b2[lane]);
    float v1 = has2 ? (a1 * invd + __ldg(&b2[32 + lane])) : -INFINITY;

    float m = fmaxf(v0, v1);
#pragma unroll
    for (int off = 16; off > 0; off >>= 1)
        m = fmaxf(m, __shfl_xor_sync(0xFFFFFFFFu, m, off));

    float s = __expf(v0 - m) + (has2 ? __expf(v1 - m) : 0.f);
#pragma unroll
    for (int off = 16; off > 0; off >>= 1)
        s += __shfl_xor_sync(0xFFFFFFFFu, s, off);

    float lse = m + __logf(s);
    float* r = out + (size_t)v * D_OUT;
    r[lane] = v0 - lse;
    if (has2) r[32 + lane] = v1 - lse;
}

// ---------------- launch ----------------
extern "C" void kernel_launch(void* const* d_in, const int* in_sizes, int n_in,
                              void* d_out, int out_size) {
    const float* H   = (const float*)d_in[0];
    const float* w   = (const float*)d_in[1];
    const int*   ni  = (const int*)  d_in[2];
    const int*   ei  = (const int*)  d_in[3];
    const float* W1  = (const float*)d_in[4];
    const float* b1  = (const float*)d_in[5];
    const float* W2  = (const float*)d_in[6];
    const float* b2  = (const float*)d_in[7];
    float*       out = (float*)d_out;

    const int T = 256;
    auto blocks = [](long n, int t) { return (int)((n + t - 1) / t); };

    zero_cnt_kernel<<<blocks(ZC, T), T>>>();
    fill_kernel<<<blocks(N_INC, T), T>>>(ni, ei);
    gemm1_kernel<<<blocks(N_NODES, T), T>>>(H, W1);

    edge_gather1_kernel<<<blocks((long)N_EDGES * 32, T), T>>>(w);
    node_gather1_gemm2_kernel<<<blocks((long)N_NODES * 32, T), T>>>(W2, b1);

    edge_gather2_kernel<<<blocks((long)N_EDGES * 32, T), T>>>(w);
    node_gather2_fin_kernel<<<blocks((long)N_NODES * 32, T), T>>>(out, b2);
}